// round 6
// baseline (speedup 1.0000x reference)
#include <cuda_runtime.h>
#include <cuda_fp16.h>
#include <math_constants.h>

#define Bb 4
#define Cc 64
#define C2c 32
#define Nn 1024
#define Vv 20
#define Pp (Bb*Nn*Vv)          // 81920 points
#define NVv (Nn*Vv)            // 20480
#define BNb (Bb*Nn)            // 4096 tiles
#define OUTSZ (Bb*Cc*Nn*Vv)    // 5242880
#define EPSc 1e-5f

// -------- scratch (device globals; no allocation allowed) --------
__device__ float  g_xm[C2c*Pp];       // masked embed pre-BN, layout [c2][p]
__device__ __half g_uh[OUTSZ];        // (u + T) fp16, TILE-MAJOR: [tile][o][v]
__device__ float  g_est[64];          // embed: sum[0:32], sumsq[32:64]
__device__ float  g_cst[320];         // conv: S1,S2,S3,S4,Cx each [64]

// -------- f32x2 helpers --------
__device__ __forceinline__ unsigned long long dup2(float x) {
    unsigned long long r;
    asm("mov.b64 %0, {%1, %1};" : "=l"(r) : "f"(x));
    return r;
}
__device__ __forceinline__ void fma2(unsigned long long& d, unsigned long long a, unsigned long long b) {
    asm("fma.rn.f32x2 %0, %1, %2, %0;" : "+l"(d) : "l"(a), "l"(b));
}
__device__ __forceinline__ float2 unpk2(unsigned long long v) {
    float2 r;
    asm("mov.b64 {%0, %1}, %2;" : "=f"(r.x), "=f"(r.y) : "l"(v));
    return r;
}

// ==================== K0: zero accumulators ====================
__global__ void k0_zero() {
    int t = threadIdx.x;
    if (t < 64) g_est[t] = 0.f;
    else if (t < 384) g_cst[t - 64] = 0.f;
}

// ==================== K1: embed GEMM + masked stats ====================
__global__ void __launch_bounds__(128) k1_embed(
    const float* __restrict__ feats, const float* __restrict__ mask,
    const float* __restrict__ wE, const float* __restrict__ bE)
{
    __shared__ __align__(16) float wsh[Cc*C2c];  // [c][o]; o pairs adjacent
    __shared__ float sacc[64];
    int tid = threadIdx.x;
    for (int j = tid; j < Cc*C2c; j += 128) {
        int o = j >> 6, c = j & 63;
        wsh[c*C2c + o] = wE[j];
    }
    if (tid < 64) sacc[tid] = 0.f;
    __syncthreads();

    int t  = blockIdx.x * 128 + tid;         // 320*128 = 40960 thread-pairs
    int p0 = 2 * t;
    int b  = p0 / NVv;
    int nv = p0 - b * NVv;
    const float* fptr = feats + (size_t)b * Cc * NVv + nv;
    const ulonglong2* wsh4 = (const ulonglong2*)wsh;

    unsigned long long accA[16], accB[16];
    #pragma unroll
    for (int j = 0; j < 16; ++j) { accA[j] = 0ULL; accB[j] = 0ULL; }

    #pragma unroll 4
    for (int c = 0; c < Cc; ++c) {
        float2 f = *(const float2*)(fptr + c * NVv);
        unsigned long long fa = dup2(f.x), fb = dup2(f.y);
        #pragma unroll
        for (int j = 0; j < 8; ++j) {
            ulonglong2 w = wsh4[c*8 + j];
            fma2(accA[2*j],   w.x, fa);
            fma2(accB[2*j],   w.x, fb);
            fma2(accA[2*j+1], w.y, fa);
            fma2(accB[2*j+1], w.y, fb);
        }
    }

    float m0 = __ldg(mask + p0), m1 = __ldg(mask + p0 + 1);
    int lane = tid & 31;

    #pragma unroll
    for (int j = 0; j < 16; ++j) {
        float2 va = unpk2(accA[j]);
        float2 vb = unpk2(accB[j]);
        int o0 = 2*j, o1 = 2*j + 1;
        float b0 = __ldg(bE + o0), b1 = __ldg(bE + o1);
        float x00 = (va.x + b0) * m0;
        float x01 = (vb.x + b0) * m1;
        float x10 = (va.y + b1) * m0;
        float x11 = (vb.y + b1) * m1;
        *(float2*)(g_xm + (size_t)o0*Pp + p0) = make_float2(x00, x01);
        *(float2*)(g_xm + (size_t)o1*Pp + p0) = make_float2(x10, x11);
        float s0 = x00 + x01, q0 = x00*x00 + x01*x01;
        float s1 = x10 + x11, q1 = x10*x10 + x11*x11;
        #pragma unroll
        for (int d = 1; d <= 4; d <<= 1) {
            s0 += __shfl_xor_sync(0xffffffffu, s0, d);
            q0 += __shfl_xor_sync(0xffffffffu, q0, d);
            s1 += __shfl_xor_sync(0xffffffffu, s1, d);
            q1 += __shfl_xor_sync(0xffffffffu, q1, d);
        }
        if ((lane & 7) == 0) {
            atomicAdd(&sacc[o0], s0);      atomicAdd(&sacc[32 + o0], q0);
            atomicAdd(&sacc[o1], s1);      atomicAdd(&sacc[32 + o1], q1);
        }
    }
    __syncthreads();
    if (tid < 64) atomicAdd(&g_est[tid], sacc[tid]);
}

// ==================== K3: u/t GEMV + conv stats + fused T ====================
// 1024 blocks x 128 threads; each block 4 tiles, 2 concurrent halves.
// Thread (half, o): u-row (W1-W2) AND t-row (W2), sharing x LDS.128 reads.
// Weights stay in smem (regs ~75). Writes (u+T) fp16 tile-major, coalesced.
__global__ void __launch_bounds__(128) k3_conv(
    const float* __restrict__ mask, const float* __restrict__ wC,
    const float* __restrict__ gE, const float* __restrict__ beE)
{
    __shared__ float wshU[64*33];                  // W1-W2, row stride 33
    __shared__ float wshT[64*33];                  // W2
    __shared__ __align__(16) float xs[2][C2c*Vv];  // per-half x tile
    __shared__ float bnA[64];

    int tid  = threadIdx.x;
    int half = tid >> 6;
    int o    = tid & 63;

    for (int j = tid; j < 64*32; j += 128) {
        int oo = j >> 5, c2 = j & 31;
        float w2 = wC[oo*64 + 32 + c2];
        wshT[oo*33 + c2] = w2;
        wshU[oo*33 + c2] = wC[oo*64 + c2] - w2;
    }
    if (tid < 32) {                                // finalize embed BN
        float inv  = 1.f / (float)Pp;
        float mean = g_est[tid] * inv;
        float var  = g_est[32 + tid] * inv - mean * mean;
        float sc   = rsqrtf(var + EPSc) * __ldg(gE + tid);
        bnA[tid]      = sc;
        bnA[32 + tid] = __ldg(beE + tid) - mean * sc;
    }

    float S1 = 0.f, S2 = 0.f, S3 = 0.f, S4 = 0.f, CX = 0.f;

    #pragma unroll
    for (int it2 = 0; it2 < 2; ++it2) {
        __syncthreads();
        // load x tiles for both halves: 1280 values / 128 threads
        #pragma unroll
        for (int k = 0; k < 10; ++k) {
            int i  = tid + k * 128;
            int h  = i / 640;
            int j  = i - h * 640;
            int c2 = j / Vv, v = j - c2 * Vv;
            int tId = blockIdx.x * 4 + it2 * 2 + h;
            int p  = tId * Vv + v;
            float val = g_xm[(size_t)c2 * Pp + p];
            xs[h][c2*Vv + v] =
                fmaxf(fmaf(val, bnA[c2], bnA[32 + c2]), 0.f) * __ldg(mask + p);
        }
        __syncthreads();

        int tileId = blockIdx.x * 4 + it2 * 2 + half;
        const ulonglong2* xv = (const ulonglong2*)xs[half];

        unsigned long long ua[10], ta[10];
        #pragma unroll
        for (int q = 0; q < 10; ++q) { ua[q] = 0ULL; ta[q] = 0ULL; }

        #pragma unroll
        for (int c2 = 0; c2 < 32; ++c2) {
            unsigned long long wu = dup2(wshU[o*33 + c2]);   // conflict-free
            unsigned long long wt = dup2(wshT[o*33 + c2]);
            #pragma unroll
            for (int q = 0; q < 5; ++q) {
                ulonglong2 x = xv[c2*5 + q];
                fma2(ua[2*q],   wu, x.x);
                fma2(ua[2*q+1], wu, x.y);
                fma2(ta[2*q],   wt, x.x);
                fma2(ta[2*q+1], wt, x.y);
            }
        }

        float a[20], tt[20];
        #pragma unroll
        for (int q = 0; q < 10; ++q) {
            float2 v1 = unpk2(ua[q]); a[2*q] = v1.x; a[2*q+1] = v1.y;
            float2 v2 = unpk2(ta[q]); tt[2*q] = v2.x; tt[2*q+1] = v2.y;
        }

        float su = 0.f, qu = 0.f, st = 0.f, qt = 0.f, mxt = -CUDART_INF_F;
        #pragma unroll
        for (int v = 0; v < 20; ++v) {
            su += a[v];  qu += a[v]*a[v];
            st += tt[v]; qt += tt[v]*tt[v];
            mxt = fmaxf(mxt, tt[v]);
        }

        // store (u + T) fp16, tile-major, contiguous 40B per thread
        union { uint2 u2; __half2 h2[2]; } pk;
        uint2* up = (uint2*)g_uh + ((size_t)tileId * 64 + o) * 5;
        #pragma unroll
        for (int k = 0; k < 5; ++k) {
            pk.h2[0] = __floats2half2_rn(a[4*k]   + mxt, a[4*k+1] + mxt);
            pk.h2[1] = __floats2half2_rn(a[4*k+2] + mxt, a[4*k+3] + mxt);
            up[k] = pk.u2;
        }

        S1 += su; S2 += qu; S3 += st; S4 += qt; CX += su * st;
    }

    atomicAdd(&g_cst[o],       S1);
    atomicAdd(&g_cst[64  + o], S2);
    atomicAdd(&g_cst[128 + o], S3);
    atomicAdd(&g_cst[192 + o], S4);
    atomicAdd(&g_cst[256 + o], CX);
}

// ==================== K5: epilogue with smem transpose ====================
// Block = 8 consecutive tiles x all 64 o. Reads g_uh coalesced (uint4),
// stages in padded smem, writes out/feats/mask in 640B per-o chunks.
// out = feats + mask * relu(w * scale + shift),  w = u + T (fp16)
#define USTR 1304   // smem row stride in halves (8-div, 16B-friendly, low conflicts)
__global__ void __launch_bounds__(256) k5_out(
    const float* __restrict__ feats, const float* __restrict__ mask,
    const float* __restrict__ gC, const float* __restrict__ beC,
    float* __restrict__ out)
{
    __shared__ __align__(16) __half us[8 * USTR];   // 20864 B
    __shared__ float2 bnsm[64];

    int tid = threadIdx.x;
    int T0  = blockIdx.x * 8;                 // 512 blocks
    int b   = T0 >> 10, n0 = T0 & 1023;

    // stage u chunk: 10240 halves = 1280 uint4, coalesced
    const uint4* src = (const uint4*)(g_uh + (size_t)T0 * 1280);
    #pragma unroll
    for (int k = 0; k < 5; ++k) {
        int g = tid + k * 256;
        int n = g / 160;                      // tile-local
        ((uint4*)us)[n * (USTR/8) + (g - n*160)] = __ldg(src + g);
    }

    if (tid < 64) {                           // conv-BN finalize
        int o = tid;
        float Sa = g_cst[o], Sb = g_cst[64+o], Sc = g_cst[128+o],
              Sd = g_cst[192+o], Cx = g_cst[256+o];
        const float invM = 1.f / ((float)Bb * Nn * Vv * Vv);
        float mean = (float)Vv * (Sa + Sc) * invM;
        float ey2  = ((float)Vv * (Sb + Sd) + 2.f * Cx) * invM;
        float sc   = rsqrtf(ey2 - mean * mean + EPSc) * __ldg(gC + o);
        bnsm[o] = make_float2(sc, __ldg(beC + o) - mean * sc);
    }
    __syncthreads();

    // 2560 float4 outputs per block, 10 per thread
    #pragma unroll
    for (int k = 0; k < 10; ++k) {
        int q = tid + k * 256;
        int o = q / 40;
        int r = q - 40 * o;
        int n = r / 5;
        int j = r - 5 * n;

        uint2 raw = ((const uint2*)us)[n * (USTR/4) + o * 5 + j];
        __half2 h0 = ((const __half2*)&raw)[0];
        __half2 h1 = ((const __half2*)&raw)[1];
        float2 w0 = __half22float2(h0);
        float2 w1 = __half22float2(h1);

        float2 bn = bnsm[o];
        float sc = bn.x, sh = bn.y;

        size_t o4 = ((size_t)(b*64 + o) * 1024 + n0 + n) * 5 + j;
        float4 fe = __ldg((const float4*)feats + o4);
        float4 mk = __ldg((const float4*)mask + ((size_t)b * 1024 + n0 + n) * 5 + j);

        float4 rr;
        rr.x = fe.x + mk.x * fmaxf(fmaf(w0.x, sc, sh), 0.f);
        rr.y = fe.y + mk.y * fmaxf(fmaf(w0.y, sc, sh), 0.f);
        rr.z = fe.z + mk.z * fmaxf(fmaf(w1.x, sc, sh), 0.f);
        rr.w = fe.w + mk.w * fmaxf(fmaf(w1.y, sc, sh), 0.f);
        ((float4*)out)[o4] = rr;
    }
}

// ==================== launch ====================
extern "C" void kernel_launch(void* const* d_in, const int* in_sizes, int n_in,
                              void* d_out, int out_size) {
    const float* feats = (const float*)d_in[0];
    const float* mask  = (const float*)d_in[1];
    const float* wE    = (const float*)d_in[2];
    const float* bE    = (const float*)d_in[3];
    const float* gE    = (const float*)d_in[4];
    const float* beE   = (const float*)d_in[5];
    const float* wC    = (const float*)d_in[6];
    const float* gC    = (const float*)d_in[7];
    const float* beC   = (const float*)d_in[8];
    float* out = (float*)d_out;

    k0_zero<<<1, 384>>>();
    k1_embed<<<320, 128>>>(feats, mask, wE, bE);
    k3_conv<<<BNb/4, 128>>>(mask, wC, gE, beE);        // 1024 blocks
    k5_out<<<BNb/8, 256>>>(feats, mask, gC, beC, out); // 512 blocks
}

// round 8
// speedup vs baseline: 1.1841x; 1.1841x over previous
#include <cuda_runtime.h>
#include <cuda_fp16.h>
#include <math_constants.h>

#define Bb 4
#define Cc 64
#define C2c 32
#define Nn 1024
#define Vv 20
#define Pp (Bb*Nn*Vv)          // 81920 points
#define NVv (Nn*Vv)            // 20480
#define BNb (Bb*Nn)            // 4096 tiles
#define OUTSZ (Bb*Cc*Nn*Vv)    // 5242880
#define EPSc 1e-5f

// -------- scratch (device globals; no allocation allowed) --------
__device__ float  g_xm[C2c*Pp];       // masked embed pre-BN, layout [c2][p]
__device__ __half g_uh[OUTSZ];        // (u + T) fp16, TILE-MAJOR: [tile][o][v]
__device__ float  g_part[32*10*2];    // embed stat partials [c2][chunk][{s,q}]
__device__ float  g_cst[320];         // conv: S1,S2,S3,S4,Cx each [64]

// -------- f32x2 helpers --------
__device__ __forceinline__ unsigned long long dup2(float x) {
    unsigned long long r;
    asm("mov.b64 %0, {%1, %1};" : "=l"(r) : "f"(x));
    return r;
}
__device__ __forceinline__ void fma2(unsigned long long& d, unsigned long long a, unsigned long long b) {
    asm("fma.rn.f32x2 %0, %1, %2, %0;" : "+l"(d) : "l"(a), "l"(b));
}
__device__ __forceinline__ float2 unpk2(unsigned long long v) {
    float2 r;
    asm("mov.b64 {%0, %1}, %2;" : "=f"(r.x), "=f"(r.y) : "l"(v));
    return r;
}

// ==================== K1: embed GEMM (PURE — no stats) ====================
// 2 consecutive points per thread. xm = mask * (feats . wE^T + bE)
__global__ void __launch_bounds__(128) k1_embed(
    const float* __restrict__ feats, const float* __restrict__ mask,
    const float* __restrict__ wE, const float* __restrict__ bE)
{
    __shared__ __align__(16) float wsh[Cc*C2c];  // [c][o]; o pairs adjacent
    int tid = threadIdx.x;
    for (int j = tid; j < Cc*C2c; j += 128) {
        int o = j >> 6, c = j & 63;
        wsh[c*C2c + o] = wE[j];
    }
    if (blockIdx.x == 0) {                       // zero conv-stat accumulators
        for (int i = tid; i < 320; i += 128) g_cst[i] = 0.f;
    }
    __syncthreads();

    int t  = blockIdx.x * 128 + tid;         // 320*128 = 40960 thread-pairs
    int p0 = 2 * t;
    int b  = p0 / NVv;
    int nv = p0 - b * NVv;
    const float* fptr = feats + (size_t)b * Cc * NVv + nv;
    const ulonglong2* wsh4 = (const ulonglong2*)wsh;

    unsigned long long accA[16], accB[16];
    #pragma unroll
    for (int j = 0; j < 16; ++j) { accA[j] = 0ULL; accB[j] = 0ULL; }

    #pragma unroll 4
    for (int c = 0; c < Cc; ++c) {
        float2 f = *(const float2*)(fptr + c * NVv);
        unsigned long long fa = dup2(f.x), fb = dup2(f.y);
        #pragma unroll
        for (int j = 0; j < 8; ++j) {
            ulonglong2 w = wsh4[c*8 + j];
            fma2(accA[2*j],   w.x, fa);
            fma2(accB[2*j],   w.x, fb);
            fma2(accA[2*j+1], w.y, fa);
            fma2(accB[2*j+1], w.y, fb);
        }
    }

    float m0 = __ldg(mask + p0), m1 = __ldg(mask + p0 + 1);

    #pragma unroll
    for (int j = 0; j < 16; ++j) {
        float2 va = unpk2(accA[j]);
        float2 vb = unpk2(accB[j]);
        int o0 = 2*j, o1 = 2*j + 1;
        float b0 = __ldg(bE + o0), b1 = __ldg(bE + o1);
        *(float2*)(g_xm + (size_t)o0*Pp + p0) =
            make_float2((va.x + b0) * m0, (vb.x + b0) * m1);
        *(float2*)(g_xm + (size_t)o1*Pp + p0) =
            make_float2((va.y + b1) * m0, (vb.y + b1) * m1);
    }
}

// ==================== K2: embed stats (atomic-free) ====================
// 320 blocks: c2 = blk&31, chunk = blk>>5 (10 chunks x 8192 floats).
// Front-batched float4 loads (MLP=8), block reduce, plain store to g_part.
__global__ void __launch_bounds__(256) k2_stats()
{
    __shared__ float ss[8], qq[8];
    int tid = threadIdx.x;
    int c2 = blockIdx.x & 31, chunk = blockIdx.x >> 5;
    const float4* src = (const float4*)(g_xm + (size_t)c2 * Pp + chunk * 8192);

    float4 v[8];
    #pragma unroll
    for (int k = 0; k < 8; ++k) v[k] = __ldg(src + tid + k * 256);

    float s = 0.f, q = 0.f;
    #pragma unroll
    for (int k = 0; k < 8; ++k) {
        s += v[k].x + v[k].y + v[k].z + v[k].w;
        q += v[k].x*v[k].x + v[k].y*v[k].y + v[k].z*v[k].z + v[k].w*v[k].w;
    }
    #pragma unroll
    for (int d = 16; d; d >>= 1) {
        s += __shfl_xor_sync(0xffffffffu, s, d);
        q += __shfl_xor_sync(0xffffffffu, q, d);
    }
    int wid = tid >> 5;
    if ((tid & 31) == 0) { ss[wid] = s; qq[wid] = q; }
    __syncthreads();
    if (tid == 0) {
        float S = 0.f, Q = 0.f;
        #pragma unroll
        for (int w = 0; w < 8; ++w) { S += ss[w]; Q += qq[w]; }
        g_part[(c2 * 10 + chunk) * 2]     = S;
        g_part[(c2 * 10 + chunk) * 2 + 1] = Q;
    }
}

// ==================== K3: u/t GEMV + conv stats + fused T ====================
// 1024 blocks x 128 threads; each block 4 tiles, 2 concurrent halves.
// Thread (half, o): u-row (W1-W2) AND t-row (W2), sharing x LDS.128 reads.
__global__ void __launch_bounds__(128) k3_conv(
    const float* __restrict__ mask, const float* __restrict__ wC,
    const float* __restrict__ gE, const float* __restrict__ beE)
{
    __shared__ float wshU[64*33];                  // W1-W2, row stride 33
    __shared__ float wshT[64*33];                  // W2
    __shared__ __align__(16) float xs[2][C2c*Vv];  // per-half x tile
    __shared__ float bnA[64];

    int tid  = threadIdx.x;
    int half = tid >> 6;
    int o    = tid & 63;

    for (int j = tid; j < 64*32; j += 128) {
        int oo = j >> 5, c2 = j & 31;
        float w2 = wC[oo*64 + 32 + c2];
        wshT[oo*33 + c2] = w2;
        wshU[oo*33 + c2] = wC[oo*64 + c2] - w2;
    }
    if (tid < 32) {                                // finalize embed BN
        float s = 0.f, q = 0.f;
        #pragma unroll
        for (int ch = 0; ch < 10; ++ch) {
            s += g_part[(tid * 10 + ch) * 2];
            q += g_part[(tid * 10 + ch) * 2 + 1];
        }
        float inv  = 1.f / (float)Pp;
        float mean = s * inv;
        float var  = q * inv - mean * mean;
        float sc   = rsqrtf(var + EPSc) * __ldg(gE + tid);
        bnA[tid]      = sc;
        bnA[32 + tid] = __ldg(beE + tid) - mean * sc;
    }

    float S1 = 0.f, S2 = 0.f, S3 = 0.f, S4 = 0.f, CX = 0.f;

    #pragma unroll
    for (int it2 = 0; it2 < 2; ++it2) {
        __syncthreads();
        #pragma unroll
        for (int k = 0; k < 10; ++k) {
            int i  = tid + k * 128;
            int h  = i / 640;
            int j  = i - h * 640;
            int c2 = j / Vv, v = j - c2 * Vv;
            int tId = blockIdx.x * 4 + it2 * 2 + h;
            int p  = tId * Vv + v;
            float val = g_xm[(size_t)c2 * Pp + p];
            xs[h][c2*Vv + v] =
                fmaxf(fmaf(val, bnA[c2], bnA[32 + c2]), 0.f) * __ldg(mask + p);
        }
        __syncthreads();

        int tileId = blockIdx.x * 4 + it2 * 2 + half;
        const ulonglong2* xv = (const ulonglong2*)xs[half];

        unsigned long long ua[10], ta[10];
        #pragma unroll
        for (int q = 0; q < 10; ++q) { ua[q] = 0ULL; ta[q] = 0ULL; }

        #pragma unroll
        for (int c2 = 0; c2 < 32; ++c2) {
            unsigned long long wu = dup2(wshU[o*33 + c2]);   // conflict-free
            unsigned long long wt = dup2(wshT[o*33 + c2]);
            #pragma unroll
            for (int q = 0; q < 5; ++q) {
                ulonglong2 x = xv[c2*5 + q];
                fma2(ua[2*q],   wu, x.x);
                fma2(ua[2*q+1], wu, x.y);
                fma2(ta[2*q],   wt, x.x);
                fma2(ta[2*q+1], wt, x.y);
            }
        }

        float a[20], tt[20];
        #pragma unroll
        for (int q = 0; q < 10; ++q) {
            float2 v1 = unpk2(ua[q]); a[2*q] = v1.x; a[2*q+1] = v1.y;
            float2 v2 = unpk2(ta[q]); tt[2*q] = v2.x; tt[2*q+1] = v2.y;
        }

        float su = 0.f, qu = 0.f, st = 0.f, qt = 0.f, mxt = -CUDART_INF_F;
        #pragma unroll
        for (int v = 0; v < 20; ++v) {
            su += a[v];  qu += a[v]*a[v];
            st += tt[v]; qt += tt[v]*tt[v];
            mxt = fmaxf(mxt, tt[v]);
        }

        // store (u + T) fp16, tile-major, contiguous 40B per thread
        union { uint2 u2; __half2 h2[2]; } pk;
        uint2* up = (uint2*)g_uh + ((size_t)tileId * 64 + o) * 5;
        #pragma unroll
        for (int k = 0; k < 5; ++k) {
            pk.h2[0] = __floats2half2_rn(a[4*k]   + mxt, a[4*k+1] + mxt);
            pk.h2[1] = __floats2half2_rn(a[4*k+2] + mxt, a[4*k+3] + mxt);
            up[k] = pk.u2;
        }

        S1 += su; S2 += qu; S3 += st; S4 += qt; CX += su * st;
    }

    atomicAdd(&g_cst[o],       S1);
    atomicAdd(&g_cst[64  + o], S2);
    atomicAdd(&g_cst[128 + o], S3);
    atomicAdd(&g_cst[192 + o], S4);
    atomicAdd(&g_cst[256 + o], CX);
}

// ==================== K5: epilogue with smem transpose ====================
// Block = 4 consecutive tiles x all 64 o (1024 blocks).
// out = feats + mask * relu(w * scale + shift),  w = u + T (fp16)
#define USTR 1304   // smem row stride in halves
__global__ void __launch_bounds__(256) k5_out(
    const float* __restrict__ feats, const float* __restrict__ mask,
    const float* __restrict__ gC, const float* __restrict__ beC,
    float* __restrict__ out)
{
    __shared__ __align__(16) __half us[4 * USTR];   // 10432 B
    __shared__ float2 bnsm[64];

    int tid = threadIdx.x;
    int T0  = blockIdx.x * 4;                 // 1024 blocks
    int b   = T0 >> 10, n0 = T0 & 1023;

    // stage u chunk: 5120 halves = 640 uint4, coalesced (2 full + 1 half step)
    const uint4* src = (const uint4*)(g_uh + (size_t)T0 * 1280);
    {
        int g0 = tid,        n_0 = g0 / 160;
        int g1 = tid + 256,  n_1 = g1 / 160;
        uint4 v0 = __ldg(src + g0);
        uint4 v1 = __ldg(src + g1);
        uint4 v2;
        int g2 = tid + 512, n_2 = g2 / 160;
        if (tid < 128) v2 = __ldg(src + g2);
        ((uint4*)us)[n_0 * (USTR/8) + (g0 - n_0*160)] = v0;
        ((uint4*)us)[n_1 * (USTR/8) + (g1 - n_1*160)] = v1;
        if (tid < 128)
            ((uint4*)us)[n_2 * (USTR/8) + (g2 - n_2*160)] = v2;
    }

    if (tid < 64) {                           // conv-BN finalize
        int o = tid;
        float Sa = g_cst[o], Sb = g_cst[64+o], Sc = g_cst[128+o],
              Sd = g_cst[192+o], Cx = g_cst[256+o];
        const float invM = 1.f / ((float)Bb * Nn * Vv * Vv);
        float mean = (float)Vv * (Sa + Sc) * invM;
        float ey2  = ((float)Vv * (Sb + Sd) + 2.f * Cx) * invM;
        float sc   = rsqrtf(ey2 - mean * mean + EPSc) * __ldg(gC + o);
        bnsm[o] = make_float2(sc, __ldg(beC + o) - mean * sc);
    }
    __syncthreads();

    // 1280 float4 outputs per block, 5 per thread
    #pragma unroll
    for (int k = 0; k < 5; ++k) {
        int q = tid + k * 256;
        int o = q / 20;
        int r = q - 20 * o;
        int n = r / 5;
        int j = r - 5 * n;

        uint2 raw = ((const uint2*)us)[n * (USTR/4) + o * 5 + j];
        __half2 h0 = ((const __half2*)&raw)[0];
        __half2 h1 = ((const __half2*)&raw)[1];
        float2 w0 = __half22float2(h0);
        float2 w1 = __half22float2(h1);

        float2 bn = bnsm[o];
        float sc = bn.x, sh = bn.y;

        size_t o4 = ((size_t)(b*64 + o) * 1024 + n0 + n) * 5 + j;
        float4 fe = __ldg((const float4*)feats + o4);
        float4 mk = __ldg((const float4*)mask + ((size_t)b * 1024 + n0 + n) * 5 + j);

        float4 rr;
        rr.x = fe.x + mk.x * fmaxf(fmaf(w0.x, sc, sh), 0.f);
        rr.y = fe.y + mk.y * fmaxf(fmaf(w0.y, sc, sh), 0.f);
        rr.z = fe.z + mk.z * fmaxf(fmaf(w1.x, sc, sh), 0.f);
        rr.w = fe.w + mk.w * fmaxf(fmaf(w1.y, sc, sh), 0.f);
        ((float4*)out)[o4] = rr;
    }
}

// ==================== launch ====================
extern "C" void kernel_launch(void* const* d_in, const int* in_sizes, int n_in,
                              void* d_out, int out_size) {
    const float* feats = (const float*)d_in[0];
    const float* mask  = (const float*)d_in[1];
    const float* wE    = (const float*)d_in[2];
    const float* bE    = (const float*)d_in[3];
    const float* gE    = (const float*)d_in[4];
    const float* beE   = (const float*)d_in[5];
    const float* wC    = (const float*)d_in[6];
    const float* gC    = (const float*)d_in[7];
    const float* beC   = (const float*)d_in[8];
    float* out = (float*)d_out;

    k1_embed<<<320, 128>>>(feats, mask, wE, bE);
    k2_stats<<<320, 256>>>();
    k3_conv<<<BNb/4, 128>>>(mask, wC, gE, beE);        // 1024 blocks
    k5_out<<<BNb/4, 256>>>(feats, mask, gC, beC, out); // 1024 blocks
}

// round 9
// speedup vs baseline: 1.2886x; 1.0883x over previous
#include <cuda_runtime.h>
#include <cuda_fp16.h>
#include <math_constants.h>

#define Bb 4
#define Cc 64
#define C2c 32
#define Nn 1024
#define Vv 20
#define Pp (Bb*Nn*Vv)          // 81920 points
#define NVv (Nn*Vv)            // 20480
#define BNb (Bb*Nn)            // 4096 tiles
#define OUTSZ (Bb*Cc*Nn*Vv)    // 5242880
#define EPSc 1e-5f

#define NBLK 296               // 2 blocks/SM x 148 SMs — full single wave
#define NTHR 256
#define TOT  (NBLK*NTHR)       // 75776 threads
#define USTR 1304              // k5 smem row stride in halves

// -------- scratch (device globals; no allocation allowed) --------
__device__ float    g_xm[C2c*Pp];     // masked embed pre-BN, layout [c2][p]
__device__ __half   g_uh[OUTSZ];      // (u + T) fp16, TILE-MAJOR: [tile][o][v]
__device__ float    g_part[320*2];    // embed stat partials [unit][{s,q}]
__device__ float    g_cst[320];       // conv: S1,S2,S3,S4,Cx each [64]
__device__ unsigned g_barc[3];        // rotating barrier counters (zero-init)

// -------- f32x2 helpers --------
__device__ __forceinline__ unsigned long long dup2(float x) {
    unsigned long long r;
    asm("mov.b64 %0, {%1, %1};" : "=l"(r) : "f"(x));
    return r;
}
__device__ __forceinline__ void fma2(unsigned long long& d, unsigned long long a, unsigned long long b) {
    asm("fma.rn.f32x2 %0, %1, %2, %0;" : "+l"(d) : "l"(a), "l"(b));
}
__device__ __forceinline__ float2 unpk2(unsigned long long v) {
    float2 r;
    asm("mov.b64 {%0, %1}, %2;" : "=f"(r.x), "=f"(r.y) : "l"(v));
    return r;
}

// -------- device-wide barrier (all NBLK blocks resident by construction) ---
// Barrier i uses counter i; its last arriver resets counter (i+2)%3, which is
// not reused until two barriers later (or next launch) — the intervening
// release/acquire fences order the reset before any reuse. Counters are
// zero-initialized and the rotation leaves each counter zeroed before reuse,
// so the scheme survives arbitrarily many graph replays with no host reset.
__device__ __forceinline__ void gbar(int i) {
    __syncthreads();
    if (threadIdx.x == 0) {
        __threadfence();                              // publish phase data
        unsigned prev = atomicAdd(&g_barc[i], 1);
        if (prev == NBLK - 1)
            atomicExch(&g_barc[(i + 2) % 3], 0);      // reset two-ahead
        while (*((volatile unsigned*)&g_barc[i]) < NBLK) { }
        __threadfence();                              // acquire phase data
    }
    __syncthreads();
}

// -------- shared memory (phases reuse the same block) --------
union SmemU {
    struct { float wsh[Cc*C2c]; } p1;                              // 8 KB
    struct { float ss[8], qq[8]; } p2;
    struct { float wshU[64*33], wshT[64*33];
             float xs[4][C2c*Vv]; float bnA[64]; } p3;             // 27.4 KB
    struct { __half us[4*USTR]; float2 bnsm[64]; } p5;             // 10.9 KB
};

__global__ void __launch_bounds__(NTHR, 2) fused_all(
    const float* __restrict__ feats, const float* __restrict__ mask,
    const float* __restrict__ wE,    const float* __restrict__ bE,
    const float* __restrict__ gE,    const float* __restrict__ beE,
    const float* __restrict__ wC,    const float* __restrict__ gC,
    const float* __restrict__ beC,   float* __restrict__ out)
{
    __shared__ __align__(16) SmemU sm;
    int tid = threadIdx.x;
    int bid = blockIdx.x;

    // ================= Phase 1: embed GEMM (pure) =================
    {
        for (int j = tid; j < Cc*C2c; j += NTHR) {
            int c = j >> 5, o = j & 31;
            sm.p1.wsh[j] = wE[o*64 + c];          // [c][o], o pairs adjacent
        }
        if (bid == 0)
            for (int i = tid; i < 320; i += NTHR) g_cst[i] = 0.f;
        __syncthreads();

        const ulonglong2* wsh4 = (const ulonglong2*)sm.p1.wsh;
        int gtid = bid * NTHR + tid;
        #pragma unroll
        for (int rep = 0; rep < 2; ++rep) {
            int p = gtid + rep * TOT;
            if (p < Pp) {
                int b  = p / NVv;
                int nv = p - b * NVv;
                const float* fptr = feats + (size_t)b * Cc * NVv + nv;

                unsigned long long acc[16];
                #pragma unroll
                for (int j = 0; j < 16; ++j) acc[j] = 0ULL;

                #pragma unroll 4
                for (int c = 0; c < Cc; ++c) {
                    unsigned long long fa = dup2(__ldg(fptr + c * NVv));
                    #pragma unroll
                    for (int j = 0; j < 8; ++j) {
                        ulonglong2 w = wsh4[c*8 + j];
                        fma2(acc[2*j],   w.x, fa);
                        fma2(acc[2*j+1], w.y, fa);
                    }
                }
                float m = __ldg(mask + p);
                #pragma unroll
                for (int j = 0; j < 16; ++j) {
                    float2 v = unpk2(acc[j]);
                    g_xm[(size_t)(2*j)  *Pp + p] = (v.x + __ldg(bE + 2*j))   * m;
                    g_xm[(size_t)(2*j+1)*Pp + p] = (v.y + __ldg(bE + 2*j+1)) * m;
                }
            }
        }
    }
    gbar(0);

    // ================= Phase 2: embed stats (atomic-free) =================
    {
        #pragma unroll
        for (int rep = 0; rep < 2; ++rep) {
            int u = bid + rep * NBLK;
            if (u >= 320) break;
            __syncthreads();
            int c2 = u / 10, chunk = u - c2 * 10;
            const float4* src = (const float4*)(g_xm + (size_t)c2 * Pp + chunk * 8192);

            float4 v[8];
            #pragma unroll
            for (int k = 0; k < 8; ++k) v[k] = __ldg(src + tid + k * 256);
            float s = 0.f, q = 0.f;
            #pragma unroll
            for (int k = 0; k < 8; ++k) {
                s += v[k].x + v[k].y + v[k].z + v[k].w;
                q += v[k].x*v[k].x + v[k].y*v[k].y + v[k].z*v[k].z + v[k].w*v[k].w;
            }
            #pragma unroll
            for (int d = 16; d; d >>= 1) {
                s += __shfl_xor_sync(0xffffffffu, s, d);
                q += __shfl_xor_sync(0xffffffffu, q, d);
            }
            int wid = tid >> 5;
            if ((tid & 31) == 0) { sm.p2.ss[wid] = s; sm.p2.qq[wid] = q; }
            __syncthreads();
            if (tid == 0) {
                float S = 0.f, Q = 0.f;
                #pragma unroll
                for (int w = 0; w < 8; ++w) { S += sm.p2.ss[w]; Q += sm.p2.qq[w]; }
                g_part[u*2]     = S;
                g_part[u*2 + 1] = Q;
            }
        }
    }
    gbar(1);

    // ================= Phase 3: u/t GEMV + conv stats + fused T =========
    {
        for (int j = tid; j < 64*32; j += NTHR) {
            int oo = j >> 5, c2 = j & 31;
            float w2 = wC[oo*64 + 32 + c2];
            sm.p3.wshT[oo*33 + c2] = w2;
            sm.p3.wshU[oo*33 + c2] = wC[oo*64 + c2] - w2;
        }
        if (tid < 32) {                                // finalize embed BN
            float s = 0.f, q = 0.f;
            #pragma unroll
            for (int ch = 0; ch < 10; ++ch) {
                s += g_part[(tid*10 + ch)*2];
                q += g_part[(tid*10 + ch)*2 + 1];
            }
            float inv  = 1.f / (float)Pp;
            float mean = s * inv;
            float var  = q * inv - mean * mean;
            float sc   = rsqrtf(var + EPSc) * __ldg(gE + tid);
            sm.p3.bnA[tid]      = sc;
            sm.p3.bnA[32 + tid] = __ldg(beE + tid) - mean * sc;
        }

        int quarter = tid >> 6;
        int o       = tid & 63;
        float S1 = 0.f, S2 = 0.f, S3 = 0.f, S4 = 0.f, CX = 0.f;

        #pragma unroll
        for (int it = 0; it < 4; ++it) {
            __syncthreads();
            // stage 4 tiles of x: 2560 values / 256 threads
            #pragma unroll
            for (int k = 0; k < 10; ++k) {
                int i  = tid + k * NTHR;
                int h  = i / 640;
                int j  = i - h * 640;
                int c2 = j / Vv, v = j - c2 * Vv;
                int tId = bid * 4 + h + it * (NBLK*4);
                float x = 0.f;
                if (tId < BNb) {
                    int p = tId * Vv + v;
                    float val = g_xm[(size_t)c2 * Pp + p];
                    x = fmaxf(fmaf(val, sm.p3.bnA[c2], sm.p3.bnA[32 + c2]), 0.f)
                        * __ldg(mask + p);
                }
                sm.p3.xs[h][c2*Vv + v] = x;
            }
            __syncthreads();

            int tileId = bid * 4 + quarter + it * (NBLK*4);
            if (tileId < BNb) {
                const ulonglong2* xv = (const ulonglong2*)sm.p3.xs[quarter];

                unsigned long long ua[10], ta[10];
                #pragma unroll
                for (int q = 0; q < 10; ++q) { ua[q] = 0ULL; ta[q] = 0ULL; }

                #pragma unroll
                for (int c2 = 0; c2 < 32; ++c2) {
                    unsigned long long wu = dup2(sm.p3.wshU[o*33 + c2]);
                    unsigned long long wt = dup2(sm.p3.wshT[o*33 + c2]);
                    #pragma unroll
                    for (int q = 0; q < 5; ++q) {
                        ulonglong2 x = xv[c2*5 + q];
                        fma2(ua[2*q],   wu, x.x);
                        fma2(ua[2*q+1], wu, x.y);
                        fma2(ta[2*q],   wt, x.x);
                        fma2(ta[2*q+1], wt, x.y);
                    }
                }

                float a[20], tt[20];
                #pragma unroll
                for (int q = 0; q < 10; ++q) {
                    float2 v1 = unpk2(ua[q]); a[2*q]  = v1.x; a[2*q+1]  = v1.y;
                    float2 v2 = unpk2(ta[q]); tt[2*q] = v2.x; tt[2*q+1] = v2.y;
                }

                float su = 0.f, qu = 0.f, st = 0.f, qt = 0.f, mxt = -CUDART_INF_F;
                #pragma unroll
                for (int v = 0; v < 20; ++v) {
                    su += a[v];  qu += a[v]*a[v];
                    st += tt[v]; qt += tt[v]*tt[v];
                    mxt = fmaxf(mxt, tt[v]);
                }

                union { uint2 u2; __half2 h2[2]; } pk;
                uint2* up = (uint2*)g_uh + ((size_t)tileId * 64 + o) * 5;
                #pragma unroll
                for (int k = 0; k < 5; ++k) {
                    pk.h2[0] = __floats2half2_rn(a[4*k]   + mxt, a[4*k+1] + mxt);
                    pk.h2[1] = __floats2half2_rn(a[4*k+2] + mxt, a[4*k+3] + mxt);
                    up[k] = pk.u2;
                }
                S1 += su; S2 += qu; S3 += st; S4 += qt; CX += su * st;
            }
        }

        atomicAdd(&g_cst[o],       S1);
        atomicAdd(&g_cst[64  + o], S2);
        atomicAdd(&g_cst[128 + o], S3);
        atomicAdd(&g_cst[192 + o], S4);
        atomicAdd(&g_cst[256 + o], CX);
    }
    gbar(2);

    // ================= Phase 4: epilogue =================
    {
        if (tid < 64) {                                // conv-BN finalize
            int o = tid;
            float Sa = g_cst[o], Sb = g_cst[64+o], Sc = g_cst[128+o],
                  Sd = g_cst[192+o], Cx = g_cst[256+o];
            const float invM = 1.f / ((float)Bb * Nn * Vv * Vv);
            float mean = (float)Vv * (Sa + Sc) * invM;
            float ey2  = ((float)Vv * (Sb + Sd) + 2.f * Cx) * invM;
            float sc   = rsqrtf(ey2 - mean * mean + EPSc) * __ldg(gC + o);
            sm.p5.bnsm[o] = make_float2(sc, __ldg(beC + o) - mean * sc);
        }

        #pragma unroll
        for (int it = 0; it < 4; ++it) {
            int g = bid + it * NBLK;
            if (g >= BNb/4) break;
            __syncthreads();                          // us reuse / bnsm ready
            int T0 = g * 4;
            int b  = T0 >> 10, n0 = T0 & 1023;

            const uint4* src = (const uint4*)(g_uh + (size_t)T0 * 1280);
            {
                int g0 = tid,       n_0 = g0 / 160;
                int g1 = tid + 256, n_1 = g1 / 160;
                uint4 v0 = __ldg(src + g0);
                uint4 v1 = __ldg(src + g1);
                uint4 v2;
                int g2 = tid + 512, n_2 = g2 / 160;
                if (tid < 128) v2 = __ldg(src + g2);
                ((uint4*)sm.p5.us)[n_0 * (USTR/8) + (g0 - n_0*160)] = v0;
                ((uint4*)sm.p5.us)[n_1 * (USTR/8) + (g1 - n_1*160)] = v1;
                if (tid < 128)
                    ((uint4*)sm.p5.us)[n_2 * (USTR/8) + (g2 - n_2*160)] = v2;
            }
            __syncthreads();

            #pragma unroll
            for (int k = 0; k < 5; ++k) {
                int q = tid + k * 256;
                int o = q / 20;
                int r = q - 20 * o;
                int n = r / 5;
                int j = r - 5 * n;

                uint2 raw = ((const uint2*)sm.p5.us)[n * (USTR/4) + o * 5 + j];
                float2 w0 = __half22float2(((const __half2*)&raw)[0]);
                float2 w1 = __half22float2(((const __half2*)&raw)[1]);

                float2 bn = sm.p5.bnsm[o];
                float sc = bn.x, sh = bn.y;

                size_t o4 = ((size_t)(b*64 + o) * 1024 + n0 + n) * 5 + j;
                float4 fe = __ldg((const float4*)feats + o4);
                float4 mk = __ldg((const float4*)mask + ((size_t)b * 1024 + n0 + n) * 5 + j);

                float4 rr;
                rr.x = fe.x + mk.x * fmaxf(fmaf(w0.x, sc, sh), 0.f);
                rr.y = fe.y + mk.y * fmaxf(fmaf(w0.y, sc, sh), 0.f);
                rr.z = fe.z + mk.z * fmaxf(fmaf(w1.x, sc, sh), 0.f);
                rr.w = fe.w + mk.w * fmaxf(fmaf(w1.y, sc, sh), 0.f);
                ((float4*)out)[o4] = rr;
            }
        }
    }
}

// ==================== launch ====================
extern "C" void kernel_launch(void* const* d_in, const int* in_sizes, int n_in,
                              void* d_out, int out_size) {
    const float* feats = (const float*)d_in[0];
    const float* mask  = (const float*)d_in[1];
    const float* wE    = (const float*)d_in[2];
    const float* bE    = (const float*)d_in[3];
    const float* gE    = (const float*)d_in[4];
    const float* beE   = (const float*)d_in[5];
    const float* wC    = (const float*)d_in[6];
    const float* gC    = (const float*)d_in[7];
    const float* beC   = (const float*)d_in[8];
    float* out = (float*)d_out;

    fused_all<<<NBLK, NTHR>>>(feats, mask, wE, bE, gE, beE, wC, gC, beC, out);
}

// round 11
// speedup vs baseline: 1.2926x; 1.0031x over previous
#include <cuda_runtime.h>
#include <cuda_fp16.h>
#include <math_constants.h>

#define Bb 4
#define Cc 64
#define C2c 32
#define Nn 1024
#define Vv 20
#define Pp (Bb*Nn*Vv)          // 81920 points
#define NVv (Nn*Vv)            // 20480
#define BNb (Bb*Nn)            // 4096 tiles
#define OUTSZ (Bb*Cc*Nn*Vv)    // 5242880
#define EPSc 1e-5f

#define NBLK_B 296             // kernel B: 2 blocks/SM x 148 SMs — full wave
#define NTHR 256
#define USTR 1304              // P4 smem row stride in halves

// -------- scratch (device globals; no allocation allowed) --------
__device__ float    g_xm[C2c*Pp];     // masked embed pre-BN, layout [c2][p]
__device__ __half   g_uh[OUTSZ];      // (u + T) fp16, TILE-MAJOR: [tile][o][v]
__device__ float    g_part[320*2];    // embed stat partials [unit][{s,q}]
__device__ float    g_cst[320];       // conv: S1,S2,S3,S4,Cx each [64]
__device__ unsigned g_ctr;            // monotonic barrier counter (zero-init)

// -------- f32x2 helpers --------
__device__ __forceinline__ unsigned long long dup2(float x) {
    unsigned long long r;
    asm("mov.b64 %0, {%1, %1};" : "=l"(r) : "f"(x));
    return r;
}
__device__ __forceinline__ void fma2(unsigned long long& d, unsigned long long a, unsigned long long b) {
    asm("fma.rn.f32x2 %0, %1, %2, %0;" : "+l"(d) : "l"(a), "l"(b));
}
__device__ __forceinline__ float2 unpk2(unsigned long long v) {
    float2 r;
    asm("mov.b64 {%0, %1}, %2;" : "=f"(r.x), "=f"(r.y) : "l"(v));
    return r;
}

// -------- monotonic device-wide barrier (never reset; replay-safe) --------
// At kernel start g_ctr == k*NBLK (all previous launches completed their NBLK
// increments — stream ordering). Every arrival computes the same target
// (k+1)*NBLK. No resets, no cross-kernel coupling.
__device__ __forceinline__ void gbarM(unsigned nblk) {
    __syncthreads();
    if (threadIdx.x == 0) {
        __threadfence();                              // publish phase data
        unsigned prev   = atomicAdd(&g_ctr, 1);
        unsigned target = prev - (prev % nblk) + nblk;
        while (*((volatile unsigned*)&g_ctr) < target) { }
        __threadfence();                              // acquire phase data
    }
    __syncthreads();
}

// ==================================================================
// K1: embed GEMM (pure). 320 x 256 = exactly 1 point/thread.
// No barrier, no occupancy constraint — natural residency.
// ==================================================================
__global__ void __launch_bounds__(NTHR) k1_embed(
    const float* __restrict__ feats, const float* __restrict__ mask,
    const float* __restrict__ wE,    const float* __restrict__ bE)
{
    __shared__ __align__(16) float wsh[Cc*C2c];      // [c][o]; o pairs adjacent
    int tid = threadIdx.x;
    int bid = blockIdx.x;

    for (int j = tid; j < Cc*C2c; j += NTHR) {
        int c = j >> 5, o = j & 31;
        wsh[j] = wE[o*64 + c];
    }
    if (bid == 0)
        for (int i = tid; i < 320; i += NTHR) g_cst[i] = 0.f;
    __syncthreads();

    const ulonglong2* wsh4 = (const ulonglong2*)wsh;
    int p  = bid * NTHR + tid;                        // exact: 320*256 = 81920
    int b  = p / NVv;
    int nv = p - b * NVv;
    const float* fptr = feats + (size_t)b * Cc * NVv + nv;

    unsigned long long acc[16];
    #pragma unroll
    for (int j = 0; j < 16; ++j) acc[j] = 0ULL;

    #pragma unroll 4
    for (int c = 0; c < Cc; ++c) {
        unsigned long long fa = dup2(__ldg(fptr + c * NVv));
        #pragma unroll
        for (int j = 0; j < 8; ++j) {
            ulonglong2 w = wsh4[c*8 + j];
            fma2(acc[2*j],   w.x, fa);
            fma2(acc[2*j+1], w.y, fa);
        }
    }

    float m = __ldg(mask + p);
    #pragma unroll
    for (int j = 0; j < 16; ++j) {
        float2 v = unpk2(acc[j]);
        g_xm[(size_t)(2*j)  *Pp + p] = (v.x + __ldg(bE + 2*j))   * m;
        g_xm[(size_t)(2*j+1)*Pp + p] = (v.y + __ldg(bE + 2*j+1)) * m;
    }
}

// ==================================================================
// K2: embed stats (atomic-free). 320 blocks = exactly 1 unit/block.
// ==================================================================
__global__ void __launch_bounds__(NTHR) k2_stats()
{
    __shared__ float ss[8], qq[8];
    int tid = threadIdx.x;
    int u = blockIdx.x;                               // 320 units exactly
    int c2 = u / 10, chunk = u - c2 * 10;
    const float4* src = (const float4*)(g_xm + (size_t)c2 * Pp + chunk * 8192);

    float4 v[8];
    #pragma unroll
    for (int k = 0; k < 8; ++k) v[k] = __ldg(src + tid + k * 256);
    float s = 0.f, q = 0.f;
    #pragma unroll
    for (int k = 0; k < 8; ++k) {
        s += v[k].x + v[k].y + v[k].z + v[k].w;
        q += v[k].x*v[k].x + v[k].y*v[k].y + v[k].z*v[k].z + v[k].w*v[k].w;
    }
    #pragma unroll
    for (int d = 16; d; d >>= 1) {
        s += __shfl_xor_sync(0xffffffffu, s, d);
        q += __shfl_xor_sync(0xffffffffu, q, d);
    }
    int wid = tid >> 5;
    if ((tid & 31) == 0) { ss[wid] = s; qq[wid] = q; }
    __syncthreads();
    if (tid == 0) {
        float S = 0.f, Q = 0.f;
        #pragma unroll
        for (int w = 0; w < 8; ++w) { S += ss[w]; Q += qq[w]; }
        g_part[u*2]     = S;
        g_part[u*2 + 1] = Q;
    }
}

// ==================================================================
// Kernel B: Phase 3 (u/t GEMV + conv stats + fused T) + Phase 4 (epilogue)
// 296 blocks x 256 threads, 2/SM guaranteed; one internal monotonic barrier.
// ==================================================================
union SmemB {
    struct { float wshU[64*33], wshT[64*33];
             float xs[4][C2c*Vv]; float bnA[64]; } p3;             // 27.4 KB
    struct { __half us[4*USTR]; float2 bnsm[64]; } p5;             // 10.9 KB
};

__global__ void __launch_bounds__(NTHR, 2) kB(
    const float* __restrict__ feats, const float* __restrict__ mask,
    const float* __restrict__ gE,    const float* __restrict__ beE,
    const float* __restrict__ wC,    const float* __restrict__ gC,
    const float* __restrict__ beC,   float* __restrict__ out)
{
    __shared__ __align__(16) SmemB sm;
    int tid = threadIdx.x;
    int bid = blockIdx.x;

    // ---------- Phase 3 ----------
    {
        for (int j = tid; j < 64*32; j += NTHR) {
            int oo = j >> 5, c2 = j & 31;
            float w2 = wC[oo*64 + 32 + c2];
            sm.p3.wshT[oo*33 + c2] = w2;
            sm.p3.wshU[oo*33 + c2] = wC[oo*64 + c2] - w2;
        }
        if (tid < 32) {                                // finalize embed BN
            float s = 0.f, q = 0.f;
            #pragma unroll
            for (int ch = 0; ch < 10; ++ch) {
                s += g_part[(tid*10 + ch)*2];
                q += g_part[(tid*10 + ch)*2 + 1];
            }
            float inv  = 1.f / (float)Pp;
            float mean = s * inv;
            float var  = q * inv - mean * mean;
            float sc   = rsqrtf(var + EPSc) * __ldg(gE + tid);
            sm.p3.bnA[tid]      = sc;
            sm.p3.bnA[32 + tid] = __ldg(beE + tid) - mean * sc;
        }

        int quarter = tid >> 6;
        int o       = tid & 63;
        float S1 = 0.f, S2 = 0.f, S3 = 0.f, S4 = 0.f, CX = 0.f;

        #pragma unroll
        for (int it = 0; it < 4; ++it) {
            __syncthreads();
            #pragma unroll
            for (int k = 0; k < 10; ++k) {
                int i  = tid + k * NTHR;
                int h  = i / 640;
                int j  = i - h * 640;
                int c2 = j / Vv, v = j - c2 * Vv;
                int tId = bid * 4 + h + it * (NBLK_B*4);
                float x = 0.f;
                if (tId < BNb) {
                    int p = tId * Vv + v;
                    float val = g_xm[(size_t)c2 * Pp + p];
                    x = fmaxf(fmaf(val, sm.p3.bnA[c2], sm.p3.bnA[32 + c2]), 0.f)
                        * __ldg(mask + p);
                }
                sm.p3.xs[h][c2*Vv + v] = x;
            }
            __syncthreads();

            int tileId = bid * 4 + quarter + it * (NBLK_B*4);
            if (tileId < BNb) {
                const ulonglong2* xv = (const ulonglong2*)sm.p3.xs[quarter];

                unsigned long long ua[10], ta[10];
                #pragma unroll
                for (int q = 0; q < 10; ++q) { ua[q] = 0ULL; ta[q] = 0ULL; }

                #pragma unroll
                for (int c2 = 0; c2 < 32; ++c2) {
                    unsigned long long wu = dup2(sm.p3.wshU[o*33 + c2]);
                    unsigned long long wt = dup2(sm.p3.wshT[o*33 + c2]);
                    #pragma unroll
                    for (int q = 0; q < 5; ++q) {
                        ulonglong2 x = xv[c2*5 + q];
                        fma2(ua[2*q],   wu, x.x);
                        fma2(ua[2*q+1], wu, x.y);
                        fma2(ta[2*q],   wt, x.x);
                        fma2(ta[2*q+1], wt, x.y);
                    }
                }

                float a[20], tt[20];
                #pragma unroll
                for (int q = 0; q < 10; ++q) {
                    float2 v1 = unpk2(ua[q]); a[2*q]  = v1.x; a[2*q+1]  = v1.y;
                    float2 v2 = unpk2(ta[q]); tt[2*q] = v2.x; tt[2*q+1] = v2.y;
                }

                float su = 0.f, qu = 0.f, st = 0.f, qt = 0.f, mxt = -CUDART_INF_F;
                #pragma unroll
                for (int v = 0; v < 20; ++v) {
                    su += a[v];  qu += a[v]*a[v];
                    st += tt[v]; qt += tt[v]*tt[v];
                    mxt = fmaxf(mxt, tt[v]);
                }

                union { uint2 u2; __half2 h2[2]; } pk;
                uint2* up = (uint2*)g_uh + ((size_t)tileId * 64 + o) * 5;
                #pragma unroll
                for (int k = 0; k < 5; ++k) {
                    pk.h2[0] = __floats2half2_rn(a[4*k]   + mxt, a[4*k+1] + mxt);
                    pk.h2[1] = __floats2half2_rn(a[4*k+2] + mxt, a[4*k+3] + mxt);
                    up[k] = pk.u2;
                }
                S1 += su; S2 += qu; S3 += st; S4 += qt; CX += su * st;
            }
        }

        atomicAdd(&g_cst[o],       S1);
        atomicAdd(&g_cst[64  + o], S2);
        atomicAdd(&g_cst[128 + o], S3);
        atomicAdd(&g_cst[192 + o], S4);
        atomicAdd(&g_cst[256 + o], CX);
    }
    gbarM(NBLK_B);

    // ---------- Phase 4: epilogue ----------
    {
        if (tid < 64) {                                // conv-BN finalize
            int o = tid;
            float Sa = g_cst[o], Sb = g_cst[64+o], Sc = g_cst[128+o],
                  Sd = g_cst[192+o], Cx = g_cst[256+o];
            const float invM = 1.f / ((float)Bb * Nn * Vv * Vv);
            float mean = (float)Vv * (Sa + Sc) * invM;
            float ey2  = ((float)Vv * (Sb + Sd) + 2.f * Cx) * invM;
            float sc   = rsqrtf(ey2 - mean * mean + EPSc) * __ldg(gC + o);
            sm.p5.bnsm[o] = make_float2(sc, __ldg(beC + o) - mean * sc);
        }

        #pragma unroll
        for (int it = 0; it < 4; ++it) {
            int g = bid + it * NBLK_B;
            if (g >= BNb/4) break;
            __syncthreads();                           // us reuse / bnsm ready
            int T0 = g * 4;
            int b  = T0 >> 10, n0 = T0 & 1023;

            const uint4* src = (const uint4*)(g_uh + (size_t)T0 * 1280);
            {
                int g0 = tid,       n_0 = g0 / 160;
                int g1 = tid + 256, n_1 = g1 / 160;
                uint4 v0 = __ldg(src + g0);
                uint4 v1 = __ldg(src + g1);
                uint4 v2;
                int g2 = tid + 512, n_2 = g2 / 160;
                if (tid < 128) v2 = __ldg(src + g2);
                ((uint4*)sm.p5.us)[n_0 * (USTR/8) + (g0 - n_0*160)] = v0;
                ((uint4*)sm.p5.us)[n_1 * (USTR/8) + (g1 - n_1*160)] = v1;
                if (tid < 128)
                    ((uint4*)sm.p5.us)[n_2 * (USTR/8) + (g2 - n_2*160)] = v2;
            }
            __syncthreads();

            #pragma unroll
            for (int k = 0; k < 5; ++k) {
                int q = tid + k * 256;
                int o = q / 20;
                int r = q - 20 * o;
                int n = r / 5;
                int j = r - 5 * n;

                uint2 raw = ((const uint2*)sm.p5.us)[n * (USTR/4) + o * 5 + j];
                float2 w0 = __half22float2(((const __half2*)&raw)[0]);
                float2 w1 = __half22float2(((const __half2*)&raw)[1]);

                float2 bn = sm.p5.bnsm[o];
                float sc = bn.x, sh = bn.y;

                size_t o4 = ((size_t)(b*64 + o) * 1024 + n0 + n) * 5 + j;
                float4 fe = __ldg((const float4*)feats + o4);
                float4 mk = __ldg((const float4*)mask + ((size_t)b * 1024 + n0 + n) * 5 + j);

                float4 rr;
                rr.x = fe.x + mk.x * fmaxf(fmaf(w0.x, sc, sh), 0.f);
                rr.y = fe.y + mk.y * fmaxf(fmaf(w0.y, sc, sh), 0.f);
                rr.z = fe.z + mk.z * fmaxf(fmaf(w1.x, sc, sh), 0.f);
                rr.w = fe.w + mk.w * fmaxf(fmaf(w1.y, sc, sh), 0.f);
                ((float4*)out)[o4] = rr;
            }
        }
    }
}

// ==================== launch ====================
extern "C" void kernel_launch(void* const* d_in, const int* in_sizes, int n_in,
                              void* d_out, int out_size) {
    const float* feats = (const float*)d_in[0];
    const float* mask  = (const float*)d_in[1];
    const float* wE    = (const float*)d_in[2];
    const float* bE    = (const float*)d_in[3];
    const float* gE    = (const float*)d_in[4];
    const float* beE   = (const float*)d_in[5];
    const float* wC    = (const float*)d_in[6];
    const float* gC    = (const float*)d_in[7];
    const float* beC   = (const float*)d_in[8];
    float* out = (float*)d_out;

    k1_embed<<<320, NTHR>>>(feats, mask, wE, bE);
    k2_stats<<<320, NTHR>>>();
    kB<<<NBLK_B, NTHR>>>(feats, mask, gE, beE, wC, gC, beC, out);
}